// round 1
// baseline (speedup 1.0000x reference)
#include <cuda_runtime.h>

#define TT  128
#define BSZ 64
#define DD  1024
#define HH  1024
#define NG  4096   // 4*H

typedef unsigned long long u64;

// Scratch (device globals: no allocation allowed in kernel_launch)
__device__ float g_G[(size_t)TT * BSZ * NG];   // precomputed x@Wx + b, 128 MB
__device__ float g_c[BSZ * HH];                // cell state, 256 KB

__device__ __forceinline__ u64 fma2(u64 a, u64 b, u64 c) {
    u64 d;
    asm("fma.rn.f32x2 %0, %1, %2, %3;" : "=l"(d) : "l"(a), "l"(b), "l"(c));
    return d;
}
__device__ __forceinline__ u64 pack2(float lo, float hi) {
    u64 d;
    asm("mov.b64 %0, {%1, %2};" : "=l"(d) : "f"(lo), "f"(hi));
    return d;
}
__device__ __forceinline__ void unpack2(u64 v, float& lo, float& hi) {
    asm("mov.b64 {%0, %1}, %2;" : "=f"(lo), "=f"(hi) : "l"(v));
}

// ---------------------------------------------------------------------------
// Phase 1: G[M=8192, N=4096] = X[8192,1024] @ Wx[1024,4096] + b
// 128x128 block tile, BK=8, 256 threads, 8x8 per thread, f32x2 FMAs,
// double-buffered smem with register prefetch.
// ---------------------------------------------------------------------------
__global__ __launch_bounds__(256) void gemm_pre(const float* __restrict__ X,
                                                const float* __restrict__ Wx,
                                                const float* __restrict__ bias) {
    const int N = NG, K = DD;
    __shared__ float As[2][8][128];   // [k][m] (transposed A)
    __shared__ float Bs[2][8][128];   // [k][n]

    const int tid  = threadIdx.x;
    const int bx   = blockIdx.x;   // N/128
    const int by   = blockIdx.y;   // M/128
    const int aRow = tid >> 1;         // 0..127
    const int aK4  = (tid & 1) << 2;   // 0 or 4
    const int bK   = tid >> 5;         // 0..7
    const int bN4  = (tid & 31) << 2;  // 0..124
    const int tx   = tid & 15;
    const int ty   = tid >> 4;

    const float* Ap = X  + (size_t)(by * 128) * K;
    const float* Bp = Wx + (size_t)(bx * 128);

    float4 aR = *(const float4*)(Ap + (size_t)aRow * K + aK4);
    float4 bR = *(const float4*)(Bp + (size_t)bK * N + bN4);
    As[0][aK4 + 0][aRow] = aR.x;
    As[0][aK4 + 1][aRow] = aR.y;
    As[0][aK4 + 2][aRow] = aR.z;
    As[0][aK4 + 3][aRow] = aR.w;
    *(float4*)&Bs[0][bK][bN4] = bR;
    __syncthreads();

    u64 acc[4][8];
    #pragma unroll
    for (int i = 0; i < 4; ++i)
        #pragma unroll
        for (int j = 0; j < 8; ++j) acc[i][j] = 0ull;

    const int nT = K / 8;  // 128 k-tiles
    for (int tk = 0; tk < nT; ++tk) {
        const int cur = tk & 1;
        if (tk + 1 < nT) {
            const int k0 = (tk + 1) * 8;
            aR = *(const float4*)(Ap + (size_t)aRow * K + k0 + aK4);
            bR = *(const float4*)(Bp + (size_t)(k0 + bK) * N + bN4);
        }
        #pragma unroll
        for (int kk = 0; kk < 8; ++kk) {
            // A fragment: natural row-pairs (rows ty*8+2i, ty*8+2i+1)
            const ulonglong2 a01 = *(const ulonglong2*)&As[cur][kk][ty * 8];
            const ulonglong2 a23 = *(const ulonglong2*)&As[cur][kk][ty * 8 + 4];
            u64 ap[4];
            ap[0] = a01.x; ap[1] = a01.y; ap[2] = a23.x; ap[3] = a23.y;
            float br[8];
            *(float4*)&br[0] = *(const float4*)&Bs[cur][kk][tx * 8];
            *(float4*)&br[4] = *(const float4*)&Bs[cur][kk][tx * 8 + 4];
            #pragma unroll
            for (int j = 0; j < 8; ++j) {
                const u64 bb = pack2(br[j], br[j]);
                #pragma unroll
                for (int i = 0; i < 4; ++i)
                    acc[i][j] = fma2(ap[i], bb, acc[i][j]);
            }
        }
        if (tk + 1 < nT) {
            const int nxt = cur ^ 1;
            As[nxt][aK4 + 0][aRow] = aR.x;
            As[nxt][aK4 + 1][aRow] = aR.y;
            As[nxt][aK4 + 2][aRow] = aR.z;
            As[nxt][aK4 + 3][aRow] = aR.w;
            *(float4*)&Bs[nxt][bK][bN4] = bR;
            __syncthreads();
        }
    }

    // Epilogue: G = acc + b
    float* Gp = g_G + (size_t)(by * 128) * N + (size_t)(bx * 128);
    #pragma unroll
    for (int i = 0; i < 4; ++i) {
        #pragma unroll
        for (int j = 0; j < 8; ++j) {
            float lo, hi;
            unpack2(acc[i][j], lo, hi);
            const int col = tx * 8 + j;
            const float bv = bias[bx * 128 + col];
            Gp[(size_t)(ty * 8 + 2 * i)     * N + col] = lo + bv;
            Gp[(size_t)(ty * 8 + 2 * i + 1) * N + col] = hi + bv;
        }
    }
}

// ---------------------------------------------------------------------------
// Phase 2: one kernel per timestep.
// CTA `cta` owns h-columns [cta*8, cta*8+8) and computes the 32 gate columns
// {gate*1024 + cta*8 + hl : gate in 0..3, hl in 0..7} of h@Wh, adds the
// precomputed G_t slice, applies the hard-LSTM cell, updates c and writes h.
// 256 threads: thread (tx,ty) -> 4 rows (r0..r0+3) x 2 cols (2tx, 2tx+1).
// h tile is stored transposed in smem so f32x2 row-pairs come from one LDS.128;
// Wh values are stored pre-duplicated as (w,w) u64 pairs -> no packing in loop.
// ---------------------------------------------------------------------------
__global__ __launch_bounds__(256) void lstm_step(const float* __restrict__ Wh,
                                                 float* __restrict__ out,
                                                 int t) {
    __shared__ float hT[2][32][64];     // [kk][row]
    __shared__ u64   wD[2][32][32];     // [kk][col] duplicated (w,w)
    __shared__ float gs[64][33];        // gate partials

    const int tid = threadIdx.x;
    const int cta = blockIdx.x;         // 0..127
    const int tx  = tid & 15;
    const int ty  = tid >> 4;
    const int r0  = ty * 4;

    u64 accp[4] = {0ull, 0ull, 0ull, 0ull};

    const float* Gt = g_G + (size_t)t * BSZ * NG;

    if (t > 0) {
        const float* hprev = out + (size_t)(t - 1) * BSZ * HH;
        // h load: each thread 8 consecutive k of one row (2 float4)
        const int hIdx = tid * 2;
        const int hRow = hIdx >> 3;            // 0..63
        const int hK4  = (hIdx & 7) << 2;      // 0,8,16,24
        // w load: 4 scalars per thread (one per gate-strip of 8 kk)
        const int wj   = tid & 31;
        const int wkk  = tid >> 5;             // 0..7
        const int gate = wj >> 3;
        const int ncol = gate * HH + cta * 8 + (wj & 7);
        const float* Wcol = Wh + ncol;

        float4 h0 = *(const float4*)(hprev + (size_t)hRow * HH + hK4);
        float4 h1 = *(const float4*)(hprev + (size_t)hRow * HH + hK4 + 4);
        float w0 = Wcol[(size_t)(wkk)      * NG];
        float w1 = Wcol[(size_t)(wkk + 8)  * NG];
        float w2 = Wcol[(size_t)(wkk + 16) * NG];
        float w3 = Wcol[(size_t)(wkk + 24) * NG];

        hT[0][hK4 + 0][hRow] = h0.x; hT[0][hK4 + 1][hRow] = h0.y;
        hT[0][hK4 + 2][hRow] = h0.z; hT[0][hK4 + 3][hRow] = h0.w;
        hT[0][hK4 + 4][hRow] = h1.x; hT[0][hK4 + 5][hRow] = h1.y;
        hT[0][hK4 + 6][hRow] = h1.z; hT[0][hK4 + 7][hRow] = h1.w;
        wD[0][wkk     ][wj] = pack2(w0, w0);
        wD[0][wkk + 8 ][wj] = pack2(w1, w1);
        wD[0][wkk + 16][wj] = pack2(w2, w2);
        wD[0][wkk + 24][wj] = pack2(w3, w3);
        __syncthreads();

        for (int tk = 0; tk < 32; ++tk) {
            const int cur = tk & 1;
            if (tk + 1 < 32) {
                const int k0 = (tk + 1) * 32;
                h0 = *(const float4*)(hprev + (size_t)hRow * HH + k0 + hK4);
                h1 = *(const float4*)(hprev + (size_t)hRow * HH + k0 + hK4 + 4);
                w0 = Wcol[(size_t)(k0 + wkk)      * NG];
                w1 = Wcol[(size_t)(k0 + wkk + 8)  * NG];
                w2 = Wcol[(size_t)(k0 + wkk + 16) * NG];
                w3 = Wcol[(size_t)(k0 + wkk + 24) * NG];
            }
            #pragma unroll
            for (int kk = 0; kk < 32; ++kk) {
                const ulonglong2 hp = *(const ulonglong2*)&hT[cur][kk][r0];
                const u64 wb0 = wD[cur][kk][2 * tx];
                const u64 wb1 = wD[cur][kk][2 * tx + 1];
                accp[0] = fma2(hp.x, wb0, accp[0]);
                accp[1] = fma2(hp.y, wb0, accp[1]);
                accp[2] = fma2(hp.x, wb1, accp[2]);
                accp[3] = fma2(hp.y, wb1, accp[3]);
            }
            if (tk + 1 < 32) {
                const int nxt = cur ^ 1;
                hT[nxt][hK4 + 0][hRow] = h0.x; hT[nxt][hK4 + 1][hRow] = h0.y;
                hT[nxt][hK4 + 2][hRow] = h0.z; hT[nxt][hK4 + 3][hRow] = h0.w;
                hT[nxt][hK4 + 4][hRow] = h1.x; hT[nxt][hK4 + 5][hRow] = h1.y;
                hT[nxt][hK4 + 6][hRow] = h1.z; hT[nxt][hK4 + 7][hRow] = h1.w;
                wD[nxt][wkk     ][wj] = pack2(w0, w0);
                wD[nxt][wkk + 8 ][wj] = pack2(w1, w1);
                wD[nxt][wkk + 16][wj] = pack2(w2, w2);
                wD[nxt][wkk + 24][wj] = pack2(w3, w3);
                __syncthreads();
            }
        }
    }

    // Stash gate partials to smem so the cell update can gather i/f/g/o.
    {
        float lo, hi;
        unpack2(accp[0], lo, hi); gs[r0 + 0][2 * tx    ] = lo; gs[r0 + 1][2 * tx    ] = hi;
        unpack2(accp[1], lo, hi); gs[r0 + 2][2 * tx    ] = lo; gs[r0 + 3][2 * tx    ] = hi;
        unpack2(accp[2], lo, hi); gs[r0 + 0][2 * tx + 1] = lo; gs[r0 + 1][2 * tx + 1] = hi;
        unpack2(accp[3], lo, hi); gs[r0 + 2][2 * tx + 1] = lo; gs[r0 + 3][2 * tx + 1] = hi;
    }
    __syncthreads();

    // Cell update: 512 (row, hl) pairs, 2 per thread.
    float* hout = out + (size_t)t * BSZ * HH;
    #pragma unroll
    for (int pass = 0; pass < 2; ++pass) {
        const int p    = tid + pass * 256;
        const int row  = p >> 3;
        const int hl   = p & 7;
        const int ncol = cta * 8 + hl;
        const float* Grow = Gt + (size_t)row * NG;
        const float gi = gs[row][     hl] + Grow[           ncol];
        const float gf = gs[row][ 8 + hl] + Grow[    HH +   ncol];
        const float gg = gs[row][16 + hl] + Grow[2 * HH +   ncol];
        const float go = gs[row][24 + hl] + Grow[3 * HH +   ncol];
        const float iv = __saturatef(gi + 0.5f);
        const float fv = __saturatef(gf + 0.5f);
        const float gv = fminf(fmaxf(gg, -1.0f), 1.0f);
        const float ov = __saturatef(go + 0.5f);
        const float cold = (t > 0) ? g_c[row * HH + ncol] : 0.0f;
        const float cnew = fv * cold + iv * gv;
        const float hnew = ov * fminf(fmaxf(cnew, -1.0f), 1.0f);
        g_c[row * HH + ncol] = cnew;
        hout[(size_t)row * HH + ncol] = hnew;
    }
}

// ---------------------------------------------------------------------------
extern "C" void kernel_launch(void* const* d_in, const int* in_sizes, int n_in,
                              void* d_out, int out_size) {
    const float* x  = (const float*)d_in[0];   // [T, B, D]
    const float* Wx = (const float*)d_in[1];   // [D, 4H]
    const float* Wh = (const float*)d_in[2];   // [H, 4H]
    const float* b  = (const float*)d_in[3];   // [4H]
    float* out = (float*)d_out;                // [T, B, H]

    // Phase 1: precompute G = X @ Wx + b for all timesteps.
    dim3 g1(NG / 128, (TT * BSZ) / 128);       // (32, 64)
    gemm_pre<<<g1, 256>>>(x, Wx, b);

    // Phase 2: 128 sequential fused recurrent steps.
    for (int t = 0; t < TT; ++t) {
        lstm_step<<<128, 256>>>(Wh, out, t);
    }
    (void)in_sizes; (void)n_in; (void)out_size;
}